// round 3
// baseline (speedup 1.0000x reference)
#include <cuda_runtime.h>
#include <cuda_bf16.h>
#include <math.h>

// EdgeConv: out_i = tanh( sum_j MLP([x_i, x_j - x_i]) )
// Factorization:
//   layer1 pre-act per edge = x_i @ (W1a - W1b) + x_j @ W1b + b1  = P[dst] + Q[src]
//   sum_e (relu(pre)@W2 + b2) = (sum_e relu(pre)) @ W2 + deg_i * b2
// Per-node GEMMs for P,Q; per-edge gather+relu+scatter-add into R;
// final per-node GEMM R@W2 + deg*b2 -> tanh.
//
// NOTE: edge_index is int32 on device (JAX x64 disabled downcasts int64->int32).

#define MAX_N 100000

__device__ float g_P[(size_t)MAX_N * 64];
__device__ float g_Q[(size_t)MAX_N * 64];
__device__ float g_R[(size_t)MAX_N * 64];
__device__ float g_deg[MAX_N];

// ---------------------------------------------------------------------------
// Kernel A: P = x @ (W1a - W1b) + b1 ; Q = x @ W1b
// Block = 256 threads, handles 32 node rows. Weights + x rows staged in smem.
// ---------------------------------------------------------------------------
__global__ __launch_bounds__(256) void precompute_pq(
    const float* __restrict__ x, const float* __restrict__ W1,
    const float* __restrict__ b1, int N)
{
    __shared__ float sWd[64 * 64];   // W1a - W1b   [k][c]
    __shared__ float sWb[64 * 64];   // W1b         [k][c]
    __shared__ float sx[32][64];     // 32 node rows

    int tid = threadIdx.x;
    for (int i = tid; i < 64 * 64; i += 256) {
        float wa = W1[i];              // rows 0..63  (applies to x_i)
        float wb = W1[64 * 64 + i];    // rows 64..127 (applies to x_j - x_i)
        sWd[i] = wa - wb;
        sWb[i] = wb;
    }
    int rowBase = blockIdx.x * 32;
    for (int i = tid; i < 32 * 64; i += 256) {
        int r = i >> 6, c = i & 63;
        int n = rowBase + r;
        sx[r][c] = (n < N) ? x[(size_t)n * 64 + c] : 0.f;
    }
    __syncthreads();

    int c  = tid & 63;
    int r0 = tid >> 6;             // 0..3 ; this thread does rows r0, r0+4, ...
    float accP[8], accQ[8];
#pragma unroll
    for (int i = 0; i < 8; i++) { accP[i] = 0.f; accQ[i] = 0.f; }

#pragma unroll 4
    for (int k = 0; k < 64; k++) {
        float wd = sWd[k * 64 + c];
        float wb = sWb[k * 64 + c];
#pragma unroll
        for (int i = 0; i < 8; i++) {
            float xv = sx[r0 + 4 * i][k];   // broadcast within warp
            accP[i] = fmaf(xv, wd, accP[i]);
            accQ[i] = fmaf(xv, wb, accQ[i]);
        }
    }
    float bias = b1[c];
#pragma unroll
    for (int i = 0; i < 8; i++) {
        int n = rowBase + r0 + 4 * i;
        if (n < N) {
            g_P[(size_t)n * 64 + c] = accP[i] + bias;
            g_Q[(size_t)n * 64 + c] = accQ[i];
        }
    }
}

// ---------------------------------------------------------------------------
// Kernel B: zero R and deg
// ---------------------------------------------------------------------------
__global__ __launch_bounds__(256) void zero_accum(int N)
{
    int idx = blockIdx.x * blockDim.x + threadIdx.x;
    int stride = gridDim.x * blockDim.x;
    int n4 = N * 16;                       // R as float4 count
    float4* R4 = reinterpret_cast<float4*>(g_R);
    float4 z = make_float4(0.f, 0.f, 0.f, 0.f);
    for (int i = idx; i < n4; i += stride) R4[i] = z;
    for (int i = idx; i < N; i += stride)  g_deg[i] = 0.f;
}

// ---------------------------------------------------------------------------
// Kernel C: per edge, R[dst] += relu(P[dst] + Q[src]); deg[dst] += 1
// 4 edges per warp; 8 lanes per edge; each lane handles 8 floats (2 x float4).
// red.global.add.v4.f32 (sm_90+ vector reduction, no return).
// ---------------------------------------------------------------------------
__global__ __launch_bounds__(256) void edge_scatter(
    const int* __restrict__ ei, int E, int N)
{
    int gw     = (blockIdx.x * blockDim.x + threadIdx.x) >> 5;
    int lane   = threadIdx.x & 31;
    int sub    = lane >> 3;      // edge slot within warp (0..3)
    int l8     = lane & 7;       // lane within edge group
    int nwarps = (gridDim.x * blockDim.x) >> 5;

    for (int e0 = gw * 4; e0 < E; e0 += nwarps * 4) {
        int e = e0 + sub;
        if (e >= E) continue;
        int s = ei[e];            // src j
        int d = ei[E + e];        // dst i
        // defensive clamp (degrades to wrong-answer instead of fault)
        if ((unsigned)s >= (unsigned)N || (unsigned)d >= (unsigned)N) continue;

        const float4* P4 = reinterpret_cast<const float4*>(g_P + (size_t)d * 64);
        const float4* Q4 = reinterpret_cast<const float4*>(g_Q + (size_t)s * 64);
        float4 p0 = P4[l8 * 2],     q0 = Q4[l8 * 2];
        float4 p1 = P4[l8 * 2 + 1], q1 = Q4[l8 * 2 + 1];

        float4 h0, h1;
        h0.x = fmaxf(p0.x + q0.x, 0.f);  h0.y = fmaxf(p0.y + q0.y, 0.f);
        h0.z = fmaxf(p0.z + q0.z, 0.f);  h0.w = fmaxf(p0.w + q0.w, 0.f);
        h1.x = fmaxf(p1.x + q1.x, 0.f);  h1.y = fmaxf(p1.y + q1.y, 0.f);
        h1.z = fmaxf(p1.z + q1.z, 0.f);  h1.w = fmaxf(p1.w + q1.w, 0.f);

        float* dst0 = g_R + (size_t)d * 64 + l8 * 8;
        asm volatile("red.global.add.v4.f32 [%0], {%1, %2, %3, %4};"
                     :: "l"(dst0), "f"(h0.x), "f"(h0.y), "f"(h0.z), "f"(h0.w)
                     : "memory");
        asm volatile("red.global.add.v4.f32 [%0], {%1, %2, %3, %4};"
                     :: "l"(dst0 + 4), "f"(h1.x), "f"(h1.y), "f"(h1.z), "f"(h1.w)
                     : "memory");
        if (l8 == 0) atomicAdd(&g_deg[d], 1.0f);
    }
}

// ---------------------------------------------------------------------------
// Kernel D: out = tanh(R @ W2 + deg * b2)
// ---------------------------------------------------------------------------
__global__ __launch_bounds__(256) void finalize(
    const float* __restrict__ W2, const float* __restrict__ b2,
    float* __restrict__ out, int N)
{
    __shared__ float sW[64 * 64];
    __shared__ float sR[32][64];

    int tid = threadIdx.x;
    for (int i = tid; i < 64 * 64; i += 256) sW[i] = W2[i];

    int rowBase = blockIdx.x * 32;
    for (int i = tid; i < 32 * 64; i += 256) {
        int r = i >> 6, c = i & 63;
        int n = rowBase + r;
        sR[r][c] = (n < N) ? g_R[(size_t)n * 64 + c] : 0.f;
    }
    __syncthreads();

    int c  = tid & 63;
    int r0 = tid >> 6;
    float acc[8];
#pragma unroll
    for (int i = 0; i < 8; i++) acc[i] = 0.f;

#pragma unroll 4
    for (int k = 0; k < 64; k++) {
        float w = sW[k * 64 + c];
#pragma unroll
        for (int i = 0; i < 8; i++)
            acc[i] = fmaf(sR[r0 + 4 * i][k], w, acc[i]);
    }
    float bias = b2[c];
#pragma unroll
    for (int i = 0; i < 8; i++) {
        int n = rowBase + r0 + 4 * i;
        if (n < N)
            out[(size_t)n * 64 + c] = tanhf(acc[i] + g_deg[n] * bias);
    }
}

// ---------------------------------------------------------------------------
extern "C" void kernel_launch(void* const* d_in, const int* in_sizes, int n_in,
                              void* d_out, int out_size)
{
    const float* x  = (const float*)d_in[0];
    const int*   ei = (const int*)d_in[1];     // int32 (JAX x64 disabled)
    const float* W1 = (const float*)d_in[2];
    const float* b1 = (const float*)d_in[3];
    const float* W2 = (const float*)d_in[4];
    const float* b2 = (const float*)d_in[5];
    float* out = (float*)d_out;

    int N = in_sizes[0] / 64;
    int E = in_sizes[1] / 2;
    if (N > MAX_N) N = MAX_N;

    int nodeBlocks = (N + 31) / 32;

    precompute_pq<<<nodeBlocks, 256>>>(x, W1, b1, N);
    zero_accum<<<592, 256>>>(N);
    edge_scatter<<<1184, 256>>>(ei, E, N);
    finalize<<<nodeBlocks, 256>>>(W2, b2, out, N);
}